// round 1
// baseline (speedup 1.0000x reference)
#include <cuda_runtime.h>
#include <cuda_bf16.h>
#include <cstdint>

// ============================================================================
// DeformableCurrents: e_ss - 2 e_st + e_tt
//   == sum over combined set (src ∪ tar) of K(c_p,c_q) * (w_p . w_q)
// with w = +normal for src triangles, w = -normal for targets.
//
// Plan:
//   prep_kernel : build combined arrays
//       g_I[2t]   = {cx, cy, cz, |c|^2}      g_I[2t+1] = {wx, wy, wz, 0}
//       g_J[2t]   = {-2cx,-2cy,-2cz, 1+|c|^2} g_J[2t+1] = {wx, wy, wz, 0}
//   pair_kernel : all-pairs; block = (i-chunk of 1024) x (j-chunk of total/32),
//       each thread owns 4 i-points in regs, j staged in smem tiles of 128.
//       denom = a_i + b_j + (-2c_j).c_i ; acc += (n_i.n_j) * rcp(denom)
//   reduce_kernel : deterministic double-precision sum of block partials.
// ============================================================================

#define THREADS   256
#define IPT       4           // i-points per thread
#define ICHUNK    (THREADS * IPT)   // 1024
#define TJ        128         // j-tile in shared
#define JSPLIT    32          // grid.y
#define MAX_PTS   20480       // >= padded (N+M)

__device__ float4 g_I[2 * MAX_PTS];
__device__ float4 g_J[2 * MAX_PTS];
__device__ double g_partials[1024];

// ----------------------------------------------------------------------------
__global__ void prep_kernel(const float* __restrict__ verts,
                            const float* __restrict__ tnorm,
                            const float* __restrict__ tcent,
                            const int*   __restrict__ sidx,
                            int N, int M, int total_pad)
{
    int t = blockIdx.x * blockDim.x + threadIdx.x;
    if (t >= total_pad) return;

    float cx = 0.f, cy = 0.f, cz = 0.f;
    float wx = 0.f, wy = 0.f, wz = 0.f;

    if (t < N) {
        int i0 = sidx[3 * t + 0];
        int i1 = sidx[3 * t + 1];
        int i2 = sidx[3 * t + 2];
        float ax = verts[3 * i0], ay = verts[3 * i0 + 1], az = verts[3 * i0 + 2];
        float bx = verts[3 * i1], by = verts[3 * i1 + 1], bz = verts[3 * i1 + 2];
        float gx = verts[3 * i2], gy = verts[3 * i2 + 1], gz = verts[3 * i2 + 2];
        // normals = 0.5 * cross(a - b, c - b)
        float e1x = ax - bx, e1y = ay - by, e1z = az - bz;
        float e2x = gx - bx, e2y = gy - by, e2z = gz - bz;
        wx = 0.5f * (e1y * e2z - e1z * e2y);
        wy = 0.5f * (e1z * e2x - e1x * e2z);
        wz = 0.5f * (e1x * e2y - e1y * e2x);
        cx = (ax + bx + gx) * (1.0f / 3.0f);
        cy = (ay + by + gy) * (1.0f / 3.0f);
        cz = (az + bz + gz) * (1.0f / 3.0f);
    } else if (t < N + M) {
        int j = t - N;
        cx = tcent[3 * j];  cy = tcent[3 * j + 1];  cz = tcent[3 * j + 2];
        wx = -tnorm[3 * j]; wy = -tnorm[3 * j + 1]; wz = -tnorm[3 * j + 2];
    }
    // padding rows keep w = 0 -> contribute nothing

    float a2 = cx * cx + cy * cy + cz * cz;
    g_I[2 * t]     = make_float4(cx, cy, cz, a2);
    g_I[2 * t + 1] = make_float4(wx, wy, wz, 0.f);
    g_J[2 * t]     = make_float4(-2.f * cx, -2.f * cy, -2.f * cz, 1.f + a2);
    g_J[2 * t + 1] = make_float4(wx, wy, wz, 0.f);
}

// ----------------------------------------------------------------------------
__global__ __launch_bounds__(THREADS)
void pair_kernel(int total_pad)
{
    __shared__ float4 sj[2 * TJ];      // 4 KB
    __shared__ double rbuf[THREADS];   // 2 KB

    const int tid = threadIdx.x;
    const int ibase = blockIdx.x * ICHUNK;
    const int chunk = total_pad / JSPLIT;     // multiple of TJ (total_pad % 4096 == 0)
    const int jbeg = blockIdx.y * chunk;
    const int jend = jbeg + chunk;

    // Load my IPT i-points into registers.
    float4 ic[IPT], iw[IPT];
    float acc[IPT];
#pragma unroll
    for (int u = 0; u < IPT; u++) {
        int i = ibase + u * THREADS + tid;
        ic[u] = g_I[2 * i];
        iw[u] = g_I[2 * i + 1];
        acc[u] = 0.f;
    }

    for (int jt = jbeg; jt < jend; jt += TJ) {
        __syncthreads();
        // 2*TJ == THREADS float4 loads, fully coalesced
        sj[tid] = g_J[2 * jt + tid];
        __syncthreads();

#pragma unroll 2
        for (int jj = 0; jj < TJ; jj++) {
            const float4 jc = sj[2 * jj];        // {-2cx,-2cy,-2cz, 1+|c|^2}
            const float4 jw = sj[2 * jj + 1];    // {wx, wy, wz, 0}
#pragma unroll
            for (int u = 0; u < IPT; u++) {
                float denom = ic[u].w + jc.w;                    // a_i + b_j
                denom = fmaf(jc.x, ic[u].x, denom);
                denom = fmaf(jc.y, ic[u].y, denom);
                denom = fmaf(jc.z, ic[u].z, denom);              // = 1 + d2
                float dot = iw[u].x * jw.x;
                dot = fmaf(iw[u].y, jw.y, dot);
                dot = fmaf(iw[u].z, jw.z, dot);
                float r;
                asm("rcp.approx.ftz.f32 %0, %1;" : "=f"(r) : "f"(denom));
                acc[u] = fmaf(dot, r, acc[u]);
            }
        }
    }

    // Deterministic block reduction in double.
    double s = ((double)acc[0] + (double)acc[1]) +
               ((double)acc[2] + (double)acc[3]);
    rbuf[tid] = s;
    __syncthreads();
#pragma unroll
    for (int off = THREADS / 2; off > 0; off >>= 1) {
        if (tid < off) rbuf[tid] += rbuf[tid + off];
        __syncthreads();
    }
    if (tid == 0)
        g_partials[blockIdx.y * gridDim.x + blockIdx.x] = rbuf[0];
}

// ----------------------------------------------------------------------------
__global__ void reduce_kernel(float* __restrict__ out, int nP)
{
    __shared__ double r[1024];
    int tid = threadIdx.x;
    r[tid] = (tid < nP) ? g_partials[tid] : 0.0;
    __syncthreads();
#pragma unroll
    for (int off = 512; off > 0; off >>= 1) {
        if (tid < off) r[tid] += r[tid + off];
        __syncthreads();
    }
    if (tid == 0) out[0] = (float)r[0];
}

// ----------------------------------------------------------------------------
extern "C" void kernel_launch(void* const* d_in, const int* in_sizes, int n_in,
                              void* d_out, int out_size)
{
    const float* verts = (const float*)d_in[0];   // src_vertices  (V,3)
    const float* tnorm = (const float*)d_in[1];   // tar_normals   (M,3)
    const float* tcent = (const float*)d_in[2];   // tar_centers   (M,3)
    const int*   sidx  = (const int*)  d_in[3];   // src_indices   (N,3)

    const int N = in_sizes[3] / 3;
    const int M = in_sizes[1] / 3;
    const int total = N + M;
    // pad so total_pad % (ICHUNK) == 0 and chunk % TJ == 0 (4096 = lcm need)
    const int total_pad = ((total + 4095) / 4096) * 4096;

    prep_kernel<<<(total_pad + THREADS - 1) / THREADS, THREADS>>>(
        verts, tnorm, tcent, sidx, N, M, total_pad);

    dim3 grid(total_pad / ICHUNK, JSPLIT);
    pair_kernel<<<grid, THREADS>>>(total_pad);

    const int nP = grid.x * JSPLIT;
    reduce_kernel<<<1, 1024>>>((float*)d_out, nP);
}

// round 2
// speedup vs baseline: 1.5820x; 1.5820x over previous
#include <cuda_runtime.h>
#include <cuda_bf16.h>
#include <cstdint>

// ============================================================================
// DeformableCurrents: e_ss - 2 e_st + e_tt
//   == sum over combined set (src ∪ tar) of K(c_p,c_q) * (w_p . w_q),
//   w = +normal (src), -normal (tar).  f(p,q) symmetric =>
//   S = 2 * sum_{tile_i < tile_j} Tile + sum_diag Tile.
//
// pair_kernel v2: packed fma.rn.f32x2 (2 i-points per b64 lane) +
// triangular tile schedule (T*(T+1)/2 = 136 blocks, one wave).
// j-tile staged in shared PRE-SPLATTED ({v,v} per component) so packed
// operands come straight from LDS.128 broadcast.
// ============================================================================

#define THREADS   256
#define IPT       4                  // i-points per thread (2 packed chains)
#define ICHUNK    (THREADS * IPT)    // 1024
#define TJ        256                // j-tile in shared
#define MAX_PTS   20480

typedef unsigned long long u64;

__device__ float4 g_I[2 * MAX_PTS];
__device__ float4 g_J[2 * MAX_PTS];
__device__ double g_partials[1024];

// ---- packed f32x2 helpers ---------------------------------------------------
__device__ __forceinline__ u64 fma2(u64 a, u64 b, u64 c) {
    u64 d; asm("fma.rn.f32x2 %0, %1, %2, %3;" : "=l"(d) : "l"(a), "l"(b), "l"(c));
    return d;
}
__device__ __forceinline__ u64 add2(u64 a, u64 b) {
    u64 d; asm("add.rn.f32x2 %0, %1, %2;" : "=l"(d) : "l"(a), "l"(b));
    return d;
}
__device__ __forceinline__ u64 mul2(u64 a, u64 b) {
    u64 d; asm("mul.rn.f32x2 %0, %1, %2;" : "=l"(d) : "l"(a), "l"(b));
    return d;
}
__device__ __forceinline__ u64 pack2(float lo, float hi) {
    u64 d; asm("mov.b64 %0, {%1, %2};" : "=l"(d) : "f"(lo), "f"(hi));
    return d;
}
__device__ __forceinline__ void unpack2(u64 p, float& lo, float& hi) {
    asm("mov.b64 {%0, %1}, %2;" : "=f"(lo), "=f"(hi) : "l"(p));
}
__device__ __forceinline__ float rcpf(float x) {
    float r; asm("rcp.approx.ftz.f32 %0, %1;" : "=f"(r) : "f"(x));
    return r;
}

// ----------------------------------------------------------------------------
__global__ void prep_kernel(const float* __restrict__ verts,
                            const float* __restrict__ tnorm,
                            const float* __restrict__ tcent,
                            const int*   __restrict__ sidx,
                            int N, int M, int total_pad)
{
    int t = blockIdx.x * blockDim.x + threadIdx.x;
    if (t >= total_pad) return;

    float cx = 0.f, cy = 0.f, cz = 0.f;
    float wx = 0.f, wy = 0.f, wz = 0.f;

    if (t < N) {
        int i0 = sidx[3 * t + 0];
        int i1 = sidx[3 * t + 1];
        int i2 = sidx[3 * t + 2];
        float ax = verts[3 * i0], ay = verts[3 * i0 + 1], az = verts[3 * i0 + 2];
        float bx = verts[3 * i1], by = verts[3 * i1 + 1], bz = verts[3 * i1 + 2];
        float gx = verts[3 * i2], gy = verts[3 * i2 + 1], gz = verts[3 * i2 + 2];
        float e1x = ax - bx, e1y = ay - by, e1z = az - bz;
        float e2x = gx - bx, e2y = gy - by, e2z = gz - bz;
        wx = 0.5f * (e1y * e2z - e1z * e2y);
        wy = 0.5f * (e1z * e2x - e1x * e2z);
        wz = 0.5f * (e1x * e2y - e1y * e2x);
        cx = (ax + bx + gx) * (1.0f / 3.0f);
        cy = (ay + by + gy) * (1.0f / 3.0f);
        cz = (az + bz + gz) * (1.0f / 3.0f);
    } else if (t < N + M) {
        int j = t - N;
        cx = tcent[3 * j];  cy = tcent[3 * j + 1];  cz = tcent[3 * j + 2];
        wx = -tnorm[3 * j]; wy = -tnorm[3 * j + 1]; wz = -tnorm[3 * j + 2];
    }
    // padding rows keep w = 0 -> contribute nothing (denom >= 1, rcp fine)

    float a2 = cx * cx + cy * cy + cz * cz;
    g_I[2 * t]     = make_float4(cx, cy, cz, a2);
    g_I[2 * t + 1] = make_float4(wx, wy, wz, 0.f);
    g_J[2 * t]     = make_float4(-2.f * cx, -2.f * cy, -2.f * cz, 1.f + a2);
    g_J[2 * t + 1] = make_float4(wx, wy, wz, 0.f);
}

// ----------------------------------------------------------------------------
__global__ __launch_bounds__(THREADS)
void pair_kernel(int T /* tiles of ICHUNK */)
{
    // splatted j-tile: 8 u64 per j (7 used + 1 pad for 16B alignment) = 16 KB
    __shared__ __align__(16) u64 sj[TJ * 8];
    __shared__ double rbuf[THREADS];

    const int tid = threadIdx.x;

    // triangular tile mapping: block b -> (ti, tj), ti <= tj
    int b = blockIdx.x, ti = 0, row = T;
    while (b >= row) { b -= row; ti++; row--; }
    const int tj = ti + b;
    const float scale = (ti == tj) ? 1.0f : 2.0f;

    const int ibase = ti * ICHUNK;
    const int jbeg  = tj * ICHUNK;
    const int jend  = jbeg + ICHUNK;

    // Load my IPT=4 i-points, pack pairs (0,1) and (2,3) component-wise.
    u64 pcx[2], pcy[2], pcz[2], pa2[2], pwx[2], pwy[2], pwz[2], acc[2];
#pragma unroll
    for (int c = 0; c < 2; c++) {
        int iA = ibase + (2 * c + 0) * THREADS + tid;
        int iB = ibase + (2 * c + 1) * THREADS + tid;
        float4 cA = g_I[2 * iA], wA = g_I[2 * iA + 1];
        float4 cB = g_I[2 * iB], wB = g_I[2 * iB + 1];
        pcx[c] = pack2(cA.x, cB.x);
        pcy[c] = pack2(cA.y, cB.y);
        pcz[c] = pack2(cA.z, cB.z);
        pa2[c] = pack2(cA.w, cB.w);
        pwx[c] = pack2(wA.x, wB.x);
        pwy[c] = pack2(wA.y, wB.y);
        pwz[c] = pack2(wA.z, wB.z);
        acc[c] = 0ull;
    }

    for (int jt = jbeg; jt < jend; jt += TJ) {
        __syncthreads();
        // splat-fill: each thread handles one j
        {
            int j = jt + tid;
            float4 jc = g_J[2 * j];
            float4 jw = g_J[2 * j + 1];
            float* s = (float*)&sj[tid * 8];
            s[0]  = jc.x; s[1]  = jc.x;   // -2cx
            s[2]  = jc.y; s[3]  = jc.y;   // -2cy
            s[4]  = jc.z; s[5]  = jc.z;   // -2cz
            s[6]  = jc.w; s[7]  = jc.w;   // 1+|c|^2
            s[8]  = jw.x; s[9]  = jw.x;
            s[10] = jw.y; s[11] = jw.y;
            s[12] = jw.z; s[13] = jw.z;
        }
        __syncthreads();

#pragma unroll 4
        for (int jj = 0; jj < TJ; jj++) {
            const ulonglong2* jp = (const ulonglong2*)&sj[jj * 8];
            ulonglong2 v0 = jp[0];   // {-2cx, -2cy}
            ulonglong2 v1 = jp[1];   // {-2cz, b}
            ulonglong2 v2 = jp[2];   // {wx, wy}
            ulonglong2 v3 = jp[3];   // {wz, pad}
#pragma unroll
            for (int c = 0; c < 2; c++) {
                u64 d = add2(pa2[c], v1.y);          // a_i + b_j
                d = fma2(v0.x, pcx[c], d);
                d = fma2(v0.y, pcy[c], d);
                d = fma2(v1.x, pcz[c], d);           // = 1 + |ci-cj|^2
                float d0, d1; unpack2(d, d0, d1);
                u64 r = pack2(rcpf(d0), rcpf(d1));
                u64 t = mul2(pwx[c], v2.x);
                t = fma2(pwy[c], v2.y, t);
                t = fma2(pwz[c], v3.x, t);
                acc[c] = fma2(t, r, acc[c]);
            }
        }
    }

    // Deterministic block reduction in double, with triangular scale.
    float a0, a1, a2f, a3;
    unpack2(acc[0], a0, a1);
    unpack2(acc[1], a2f, a3);
    double s = (double)scale * (((double)a0 + (double)a1) +
                                ((double)a2f + (double)a3));
    rbuf[tid] = s;
    __syncthreads();
#pragma unroll
    for (int off = THREADS / 2; off > 0; off >>= 1) {
        if (tid < off) rbuf[tid] += rbuf[tid + off];
        __syncthreads();
    }
    if (tid == 0)
        g_partials[blockIdx.x] = rbuf[0];
}

// ----------------------------------------------------------------------------
__global__ void reduce_kernel(float* __restrict__ out, int nP)
{
    __shared__ double r[1024];
    int tid = threadIdx.x;
    r[tid] = (tid < nP) ? g_partials[tid] : 0.0;
    __syncthreads();
#pragma unroll
    for (int off = 512; off > 0; off >>= 1) {
        if (tid < off) r[tid] += r[tid + off];
        __syncthreads();
    }
    if (tid == 0) out[0] = (float)r[0];
}

// ----------------------------------------------------------------------------
extern "C" void kernel_launch(void* const* d_in, const int* in_sizes, int n_in,
                              void* d_out, int out_size)
{
    const float* verts = (const float*)d_in[0];   // src_vertices  (V,3)
    const float* tnorm = (const float*)d_in[1];   // tar_normals   (M,3)
    const float* tcent = (const float*)d_in[2];   // tar_centers   (M,3)
    const int*   sidx  = (const int*)  d_in[3];   // src_indices   (N,3)

    const int N = in_sizes[3] / 3;
    const int M = in_sizes[1] / 3;
    const int total = N + M;
    const int total_pad = ((total + ICHUNK - 1) / ICHUNK) * ICHUNK;
    const int T = total_pad / ICHUNK;             // 16 for 16384 points

    prep_kernel<<<(total_pad + THREADS - 1) / THREADS, THREADS>>>(
        verts, tnorm, tcent, sidx, N, M, total_pad);

    const int nBlocks = T * (T + 1) / 2;          // 136
    pair_kernel<<<nBlocks, THREADS>>>(T);

    reduce_kernel<<<1, 1024>>>((float*)d_out, nBlocks);
}

// round 3
// speedup vs baseline: 1.8254x; 1.1538x over previous
#include <cuda_runtime.h>
#include <cuda_bf16.h>
#include <cstdint>

// ============================================================================
// DeformableCurrents: e_ss - 2 e_st + e_tt
//   == sum over combined set (src ∪ tar) of K(c_p,c_q) * (w_p . w_q),
//   w = +normal (src), -normal (tar).  f symmetric =>
//   S = 2 * sum_{tile_i < tile_j} + sum_diag.
//
// v3: packed fma.rn.f32x2 inner loop (unchanged) + occupancy fix:
//   each triangular tile-pair (1024 x 1024) split into 4 j-subtiles of 256
//   -> 544 blocks, 2 resident per SM (4 warps/SMSP) for latency hiding.
//   j-subtile == one smem tile: loaded once per block, no tile loop.
// ============================================================================

#define THREADS   256
#define IPT       4                  // i-points per thread (2 packed chains)
#define ICHUNK    (THREADS * IPT)    // 1024
#define TJ        256                // j-subtile (== smem tile)
#define JSUB      (ICHUNK / TJ)      // 4 j-subtiles per tile-pair
#define MAX_PTS   20480

typedef unsigned long long u64;

__device__ float4 g_I[2 * MAX_PTS];
__device__ float4 g_J[2 * MAX_PTS];
__device__ double g_partials[1024];

// ---- packed f32x2 helpers ---------------------------------------------------
__device__ __forceinline__ u64 fma2(u64 a, u64 b, u64 c) {
    u64 d; asm("fma.rn.f32x2 %0, %1, %2, %3;" : "=l"(d) : "l"(a), "l"(b), "l"(c));
    return d;
}
__device__ __forceinline__ u64 add2(u64 a, u64 b) {
    u64 d; asm("add.rn.f32x2 %0, %1, %2;" : "=l"(d) : "l"(a), "l"(b));
    return d;
}
__device__ __forceinline__ u64 mul2(u64 a, u64 b) {
    u64 d; asm("mul.rn.f32x2 %0, %1, %2;" : "=l"(d) : "l"(a), "l"(b));
    return d;
}
__device__ __forceinline__ u64 pack2(float lo, float hi) {
    u64 d; asm("mov.b64 %0, {%1, %2};" : "=l"(d) : "f"(lo), "f"(hi));
    return d;
}
__device__ __forceinline__ void unpack2(u64 p, float& lo, float& hi) {
    asm("mov.b64 {%0, %1}, %2;" : "=f"(lo), "=f"(hi) : "l"(p));
}
__device__ __forceinline__ float rcpf(float x) {
    float r; asm("rcp.approx.ftz.f32 %0, %1;" : "=f"(r) : "f"(x));
    return r;
}

// ----------------------------------------------------------------------------
__global__ void prep_kernel(const float* __restrict__ verts,
                            const float* __restrict__ tnorm,
                            const float* __restrict__ tcent,
                            const int*   __restrict__ sidx,
                            int N, int M, int total_pad)
{
    int t = blockIdx.x * blockDim.x + threadIdx.x;
    if (t >= total_pad) return;

    float cx = 0.f, cy = 0.f, cz = 0.f;
    float wx = 0.f, wy = 0.f, wz = 0.f;

    if (t < N) {
        int i0 = sidx[3 * t + 0];
        int i1 = sidx[3 * t + 1];
        int i2 = sidx[3 * t + 2];
        float ax = verts[3 * i0], ay = verts[3 * i0 + 1], az = verts[3 * i0 + 2];
        float bx = verts[3 * i1], by = verts[3 * i1 + 1], bz = verts[3 * i1 + 2];
        float gx = verts[3 * i2], gy = verts[3 * i2 + 1], gz = verts[3 * i2 + 2];
        float e1x = ax - bx, e1y = ay - by, e1z = az - bz;
        float e2x = gx - bx, e2y = gy - by, e2z = gz - bz;
        wx = 0.5f * (e1y * e2z - e1z * e2y);
        wy = 0.5f * (e1z * e2x - e1x * e2z);
        wz = 0.5f * (e1x * e2y - e1y * e2x);
        cx = (ax + bx + gx) * (1.0f / 3.0f);
        cy = (ay + by + gy) * (1.0f / 3.0f);
        cz = (az + bz + gz) * (1.0f / 3.0f);
    } else if (t < N + M) {
        int j = t - N;
        cx = tcent[3 * j];  cy = tcent[3 * j + 1];  cz = tcent[3 * j + 2];
        wx = -tnorm[3 * j]; wy = -tnorm[3 * j + 1]; wz = -tnorm[3 * j + 2];
    }
    // padding rows keep w = 0 -> contribute nothing (denom >= 1, rcp fine)

    float a2 = cx * cx + cy * cy + cz * cz;
    g_I[2 * t]     = make_float4(cx, cy, cz, a2);
    g_I[2 * t + 1] = make_float4(wx, wy, wz, 0.f);
    g_J[2 * t]     = make_float4(-2.f * cx, -2.f * cy, -2.f * cz, 1.f + a2);
    g_J[2 * t + 1] = make_float4(wx, wy, wz, 0.f);
}

// ----------------------------------------------------------------------------
__global__ __launch_bounds__(THREADS, 2)
void pair_kernel(int T /* tiles of ICHUNK */)
{
    // splatted j-subtile: 8 u64 per j (7 used + 1 pad) = 16 KB
    __shared__ __align__(16) u64 sj[TJ * 8];
    __shared__ double rbuf[THREADS];

    const int tid = threadIdx.x;

    // block -> (triangular tile-pair, j-subtile)
    int unit = blockIdx.x / JSUB;
    const int sub = blockIdx.x % JSUB;
    int ti = 0, row = T;
    while (unit >= row) { unit -= row; ti++; row--; }
    const int tj = ti + unit;
    const float scale = (ti == tj) ? 1.0f : 2.0f;

    const int ibase = ti * ICHUNK;
    const int jt    = tj * ICHUNK + sub * TJ;

    // Fill splatted j-subtile once.
    {
        int j = jt + tid;
        float4 jc = g_J[2 * j];
        float4 jw = g_J[2 * j + 1];
        float* s = (float*)&sj[tid * 8];
        s[0]  = jc.x; s[1]  = jc.x;   // -2cx
        s[2]  = jc.y; s[3]  = jc.y;   // -2cy
        s[4]  = jc.z; s[5]  = jc.z;   // -2cz
        s[6]  = jc.w; s[7]  = jc.w;   // 1+|c|^2
        s[8]  = jw.x; s[9]  = jw.x;
        s[10] = jw.y; s[11] = jw.y;
        s[12] = jw.z; s[13] = jw.z;
    }

    // Load my IPT=4 i-points, pack pairs (0,1) and (2,3) component-wise.
    u64 pcx[2], pcy[2], pcz[2], pa2[2], pwx[2], pwy[2], pwz[2], acc[2];
#pragma unroll
    for (int c = 0; c < 2; c++) {
        int iA = ibase + (2 * c + 0) * THREADS + tid;
        int iB = ibase + (2 * c + 1) * THREADS + tid;
        float4 cA = g_I[2 * iA], wA = g_I[2 * iA + 1];
        float4 cB = g_I[2 * iB], wB = g_I[2 * iB + 1];
        pcx[c] = pack2(cA.x, cB.x);
        pcy[c] = pack2(cA.y, cB.y);
        pcz[c] = pack2(cA.z, cB.z);
        pa2[c] = pack2(cA.w, cB.w);
        pwx[c] = pack2(wA.x, wB.x);
        pwy[c] = pack2(wA.y, wB.y);
        pwz[c] = pack2(wA.z, wB.z);
        acc[c] = 0ull;
    }

    __syncthreads();

#pragma unroll 4
    for (int jj = 0; jj < TJ; jj++) {
        const ulonglong2* jp = (const ulonglong2*)&sj[jj * 8];
        ulonglong2 v0 = jp[0];   // {-2cx, -2cy}
        ulonglong2 v1 = jp[1];   // {-2cz, b}
        ulonglong2 v2 = jp[2];   // {wx, wy}
        ulonglong2 v3 = jp[3];   // {wz, pad}
#pragma unroll
        for (int c = 0; c < 2; c++) {
            u64 d = add2(pa2[c], v1.y);          // a_i + b_j
            d = fma2(v0.x, pcx[c], d);
            d = fma2(v0.y, pcy[c], d);
            d = fma2(v1.x, pcz[c], d);           // = 1 + |ci-cj|^2
            float d0, d1; unpack2(d, d0, d1);
            u64 r = pack2(rcpf(d0), rcpf(d1));
            u64 t = mul2(pwx[c], v2.x);
            t = fma2(pwy[c], v2.y, t);
            t = fma2(pwz[c], v3.x, t);
            acc[c] = fma2(t, r, acc[c]);
        }
    }

    // Deterministic block reduction in double, with triangular scale.
    float a0, a1, a2f, a3;
    unpack2(acc[0], a0, a1);
    unpack2(acc[1], a2f, a3);
    double s = (double)scale * (((double)a0 + (double)a1) +
                                ((double)a2f + (double)a3));
    rbuf[tid] = s;
    __syncthreads();
#pragma unroll
    for (int off = THREADS / 2; off > 0; off >>= 1) {
        if (tid < off) rbuf[tid] += rbuf[tid + off];
        __syncthreads();
    }
    if (tid == 0)
        g_partials[blockIdx.x] = rbuf[0];
}

// ----------------------------------------------------------------------------
__global__ void reduce_kernel(float* __restrict__ out, int nP)
{
    __shared__ double r[1024];
    int tid = threadIdx.x;
    r[tid] = (tid < nP) ? g_partials[tid] : 0.0;
    __syncthreads();
#pragma unroll
    for (int off = 512; off > 0; off >>= 1) {
        if (tid < off) r[tid] += r[tid + off];
        __syncthreads();
    }
    if (tid == 0) out[0] = (float)r[0];
}

// ----------------------------------------------------------------------------
extern "C" void kernel_launch(void* const* d_in, const int* in_sizes, int n_in,
                              void* d_out, int out_size)
{
    const float* verts = (const float*)d_in[0];   // src_vertices  (V,3)
    const float* tnorm = (const float*)d_in[1];   // tar_normals   (M,3)
    const float* tcent = (const float*)d_in[2];   // tar_centers   (M,3)
    const int*   sidx  = (const int*)  d_in[3];   // src_indices   (N,3)

    const int N = in_sizes[3] / 3;
    const int M = in_sizes[1] / 3;
    const int total = N + M;
    const int total_pad = ((total + ICHUNK - 1) / ICHUNK) * ICHUNK;
    const int T = total_pad / ICHUNK;             // 16 for 16384 points

    prep_kernel<<<(total_pad + THREADS - 1) / THREADS, THREADS>>>(
        verts, tnorm, tcent, sidx, N, M, total_pad);

    const int nBlocks = (T * (T + 1) / 2) * JSUB;   // 544
    pair_kernel<<<nBlocks, THREADS>>>(T);

    reduce_kernel<<<1, 1024>>>((float*)d_out, nBlocks);
}